// round 4
// baseline (speedup 1.0000x reference)
#include <cuda_runtime.h>

#define HH 128
#define WW 128
#define HWSZ (128*128)
#define CIN 64
#define COUT 64
#define BATCH 8

// scratch (__device__ globals: allocation-free)
__device__ float g_off[BATCH * 27 * HWSZ];     // [b][27][H][W]: dy0,dx0,..,dy8,dx8, m0..m8
__device__ float g_wpack[576 * COUT];          // [(c*9+kk)][oc]
__device__ float g_opack[576 * 28];            // [(c*9+kk)][o] o<18 offset_w, 18..26 mod_w, 27 pad

// ---- packed f32x2 helpers (Blackwell FFMA2 path) ----
static __device__ __forceinline__ unsigned long long pk2(float lo, float hi) {
    unsigned long long r;
    asm("mov.b64 %0, {%1,%2};" : "=l"(r) : "f"(lo), "f"(hi));
    return r;
}
static __device__ __forceinline__ void fma2(unsigned long long& d,
                                            unsigned long long a,
                                            unsigned long long b) {
    asm("fma.rn.f32x2 %0, %1, %2, %0;" : "+l"(d) : "l"(a), "l"(b));
}
static __device__ __forceinline__ float2 unpk2(unsigned long long v) {
    float2 f;
    asm("mov.b64 {%0,%1}, %2;" : "=f"(f.x), "=f"(f.y) : "l"(v));
    return f;
}

// ---- prep: repack weights so oc (or o) is contiguous per (c,kk) row ----
__global__ void prep_kernel(const float* __restrict__ weight,
                            const float* __restrict__ ow,
                            const float* __restrict__ mw) {
    int i = blockIdx.x * blockDim.x + threadIdx.x;
    if (i < 576 * COUT) {
        int ck = i >> 6;
        int oc = i & 63;
        g_wpack[i] = weight[oc * 576 + ck];
    }
    if (i < 576 * 28) {
        int ck = i / 28;
        int o = i - ck * 28;
        float v = 0.f;
        if (o < 18)      v = ow[o * 576 + ck];
        else if (o < 27) v = mw[(o - 18) * 576 + ck];
        g_opack[i] = v;
    }
}

// ---- kernel 1: fused offset+modulator 3x3 conv (27 outputs), tile 32x8 ----
__global__ __launch_bounds__(128) void conv_om_kernel(const float* __restrict__ x,
                                                      const float* __restrict__ ob,
                                                      const float* __restrict__ mb) {
    __shared__ float owS[144 * 28];   // 16 channels worth of packed weights (16128 B)
    __shared__ float sxt[4 * 340];    // 4-channel input tile, 10x34 each (5440 B)

    int tid = threadIdx.x;
    int tx = tid & 31;
    int tyq = tid >> 5;                 // 0..3; each thread handles rows tyq and tyq+4
    int tw0 = blockIdx.x * 32;
    int th0 = blockIdx.y * 8;
    int b = blockIdx.z;
    const float* xb = x + (size_t)b * CIN * HWSZ;

    unsigned long long acc0[14], acc1[14];
#pragma unroll
    for (int p = 0; p < 14; p++) { acc0[p] = 0ull; acc1[p] = 0ull; }

    for (int cc = 0; cc < 4; cc++) {
        __syncthreads();
        for (int i = tid; i < 144 * 28; i += 128)
            owS[i] = g_opack[cc * 144 * 28 + i];

        for (int cb = 0; cb < 4; cb++) {
            __syncthreads();
            int cbase = cc * 16 + cb * 4;
            for (int i = tid; i < 4 * 340; i += 128) {
                int c = cbase + i / 340;
                int rem = i % 340;
                int r = rem / 34;
                int cl2 = rem - r * 34;
                int gy = th0 - 1 + r;
                int gx = tw0 - 1 + cl2;
                float v = 0.f;
                if ((unsigned)gy < HH && (unsigned)gx < WW)
                    v = xb[c * HWSZ + gy * WW + gx];
                sxt[i] = v;
            }
            __syncthreads();
#pragma unroll 1
            for (int j = 0; j < 4; j++) {
                const float* s0 = &sxt[j * 340 + tyq * 34 + tx];
                int rowbase = ((cb * 4 + j) * 9) * 28;
#pragma unroll
                for (int kk = 0; kk < 9; kk++) {
                    const int ki = kk / 3, kj = kk % 3;
                    float xv0 = s0[ki * 34 + kj];
                    float xv1 = s0[(ki + 4) * 34 + kj];
                    const unsigned long long* wr =
                        (const unsigned long long*)&owS[rowbase + kk * 28];
                    unsigned long long v0 = pk2(xv0, xv0);
                    unsigned long long v1 = pk2(xv1, xv1);
#pragma unroll
                    for (int p = 0; p < 14; p++) {
                        unsigned long long w2 = wr[p];
                        fma2(acc0[p], v0, w2);
                        fma2(acc1[p], v1, w2);
                    }
                }
            }
        }
    }

    int y0 = th0 + tyq;
    int y1 = th0 + tyq + 4;
    int xo = tw0 + tx;
    float vals0[28], vals1[28];
#pragma unroll
    for (int p = 0; p < 14; p++) {
        float2 f0 = unpk2(acc0[p]), f1 = unpk2(acc1[p]);
        vals0[2 * p] = f0.x; vals0[2 * p + 1] = f0.y;
        vals1[2 * p] = f1.x; vals1[2 * p + 1] = f1.y;
    }
#pragma unroll
    for (int o = 0; o < 27; o++) {
        float v0 = vals0[o], v1 = vals1[o];
        if (o < 18) {
            float bb = ob[o];
            v0 += bb; v1 += bb;
        } else {
            float bb = mb[o - 18];
            v0 = 2.f / (1.f + __expf(-(v0 + bb)));
            v1 = 2.f / (1.f + __expf(-(v1 + bb)));
        }
        float* dst = &g_off[((size_t)b * 27 + o) * HWSZ];
        dst[y0 * WW + xo] = v0;
        dst[y1 * WW + xo] = v1;
    }
}

// ---- bilinear tap metadata ----
struct Tap { float a00, a01, a10, a11; int o00, o01, o10, o11; };

static __device__ __forceinline__ Tap mk_tap(const float* __restrict__ offb,
                                             int pos, int ho, int xi,
                                             int ki, int kj) {
    Tap t;
    float dy = offb[(2 * ki * 3 + 2 * kj) * HWSZ + pos];
    float dx = offb[(2 * ki * 3 + 2 * kj + 1) * HWSZ + pos];
    float m  = offb[(18 + ki * 3 + kj) * HWSZ + pos];
    float fy = (float)(ho - 1 + ki) + dy;
    float fx = (float)(xi - 1 + kj) + dx;
    float fy0 = floorf(fy), fx0 = floorf(fx);
    int iy0 = (int)fy0, ix0 = (int)fx0;
    float wy = fy - fy0, wx = fx - fx0;
    bool vy0 = (unsigned)iy0 < HH;
    bool vy1 = (unsigned)(iy0 + 1) < HH;
    bool vx0 = (unsigned)ix0 < WW;
    bool vx1 = (unsigned)(ix0 + 1) < WW;
    t.a00 = (1.f - wy) * (1.f - wx) * m * ((vy0 && vx0) ? 1.f : 0.f);
    t.a01 = (1.f - wy) * wx         * m * ((vy0 && vx1) ? 1.f : 0.f);
    t.a10 = wy * (1.f - wx)         * m * ((vy1 && vx0) ? 1.f : 0.f);
    t.a11 = wy * wx                 * m * ((vy1 && vx1) ? 1.f : 0.f);
    int cy0 = min(max(iy0, 0), HH - 1);
    int cy1 = min(max(iy0 + 1, 0), HH - 1);
    int cx0 = min(max(ix0, 0), WW - 1);
    int cx1 = min(max(ix0 + 1, 0), WW - 1);
    t.o00 = cy0 * WW + cx0; t.o01 = cy0 * WW + cx1;
    t.o10 = cy1 * WW + cx0; t.o11 = cy1 * WW + cx1;
    return t;
}

// ---- kernel 2: deformable gather + GEMM.
// 1 block = 1 output row. Thread = (x-pair, oc-half): 2 positions x 32 oc.
// Per (kk,cl): 8 LDS.128 (weights, reused for both positions) + 8 LDG + 32 FFMA2.
__global__ __launch_bounds__(128) void deform_kernel(const float* __restrict__ x,
                                                     float* __restrict__ out) {
    __shared__ float wS[16 * 9 * 64];  // 36864 B: weights for 16 input channels

    int tid = threadIdx.x;
    int xq = tid & 63;        // x-pair id: positions xq and xq+64
    int oh = tid >> 6;        // oc half: oc base = oh*32
    int ho = blockIdx.x;
    int b = blockIdx.y;
    const float* xb = x + (size_t)b * CIN * HWSZ;
    const float* offb = g_off + (size_t)b * 27 * HWSZ;
    int pos0 = ho * WW + xq;
    int pos1 = pos0 + 64;

    unsigned long long acc0[16], acc1[16];
#pragma unroll
    for (int p = 0; p < 16; p++) { acc0[p] = 0ull; acc1[p] = 0ull; }

    for (int cc = 0; cc < 4; cc++) {
        __syncthreads();
        {
            const float4* src = (const float4*)(g_wpack + cc * (16 * 9 * 64));
            float4* dst = (float4*)wS;
#pragma unroll
            for (int i = 0; i < 18; i++)
                dst[tid + i * 128] = src[tid + i * 128];
        }
        __syncthreads();

#pragma unroll 1
        for (int kk = 0; kk < 9; kk++) {
            int ki = kk / 3, kj = kk - ki * 3;
            Tap t0 = mk_tap(offb, pos0, ho, xq, ki, kj);
            Tap t1 = mk_tap(offb, pos1, ho, xq + 64, ki, kj);

            const float* xc = xb + cc * 16 * HWSZ;
#pragma unroll 4
            for (int cl = 0; cl < 16; cl++) {
                const float* p = xc + cl * HWSZ;
                float v0 = t0.a00 * __ldg(p + t0.o00) + t0.a01 * __ldg(p + t0.o01)
                         + t0.a10 * __ldg(p + t0.o10) + t0.a11 * __ldg(p + t0.o11);
                float v1 = t1.a00 * __ldg(p + t1.o00) + t1.a01 * __ldg(p + t1.o01)
                         + t1.a10 * __ldg(p + t1.o10) + t1.a11 * __ldg(p + t1.o11);
                unsigned long long vv0 = pk2(v0, v0);
                unsigned long long vv1 = pk2(v1, v1);
                const ulonglong2* wr =
                    (const ulonglong2*)&wS[(cl * 9 + kk) * 64 + oh * 32];
#pragma unroll
                for (int q = 0; q < 8; q++) {
                    ulonglong2 w4 = wr[q];
                    fma2(acc0[2 * q],     vv0, w4.x);
                    fma2(acc0[2 * q + 1], vv0, w4.y);
                    fma2(acc1[2 * q],     vv1, w4.x);
                    fma2(acc1[2 * q + 1], vv1, w4.y);
                }
            }
        }
    }

    float* ob = out + ((size_t)b * COUT + oh * 32) * HWSZ;
#pragma unroll
    for (int p = 0; p < 16; p++) {
        float2 f0 = unpk2(acc0[p]);
        float2 f1 = unpk2(acc1[p]);
        ob[(2 * p) * HWSZ + pos0] = f0.x;
        ob[(2 * p + 1) * HWSZ + pos0] = f0.y;
        ob[(2 * p) * HWSZ + pos1] = f1.x;
        ob[(2 * p + 1) * HWSZ + pos1] = f1.y;
    }
}

extern "C" void kernel_launch(void* const* d_in, const int* in_sizes, int n_in,
                              void* d_out, int out_size) {
    const float* x  = (const float*)d_in[0];  // [8,64,128,128]
    const float* ow = (const float*)d_in[1];  // [18,64,3,3]
    const float* ob = (const float*)d_in[2];  // [18]
    const float* mw = (const float*)d_in[3];  // [9,64,3,3]
    const float* mb = (const float*)d_in[4];  // [9]
    const float* wt = (const float*)d_in[5];  // [64,64,3,3]
    float* out = (float*)d_out;               // [8,64,128,128]

    prep_kernel<<<144, 256>>>(wt, ow, mw);

    dim3 g1(WW / 32, HH / 8, BATCH);
    conv_om_kernel<<<g1, 128>>>(x, ob, mb);

    dim3 g2(HH, BATCH);
    deform_kernel<<<g2, 128>>>(x, out);
}

// round 5
// speedup vs baseline: 1.3268x; 1.3268x over previous
#include <cuda_runtime.h>

#define HH 128
#define WW 128
#define HWSZ (128*128)
#define CIN 64
#define COUT 64
#define BATCH 8

// scratch (__device__ globals: allocation-free)
__device__ float g_off[BATCH * 27 * HWSZ];     // [b][27][H][W]: dy0,dx0,..,dy8,dx8, m0..m8
__device__ float g_wpack[576 * COUT];          // [(c*9+kk)][oc]
__device__ float g_opack[576 * 28];            // [(c*9+kk)][o] o<18 offset_w, 18..26 mod_w, 27 pad

// ---- packed f32x2 helpers (Blackwell FFMA2 path) ----
static __device__ __forceinline__ unsigned long long pk2(float lo, float hi) {
    unsigned long long r;
    asm("mov.b64 %0, {%1,%2};" : "=l"(r) : "f"(lo), "f"(hi));
    return r;
}
static __device__ __forceinline__ void fma2(unsigned long long& d,
                                            unsigned long long a,
                                            unsigned long long b) {
    asm("fma.rn.f32x2 %0, %1, %2, %0;" : "+l"(d) : "l"(a), "l"(b));
}
static __device__ __forceinline__ float2 unpk2(unsigned long long v) {
    float2 f;
    asm("mov.b64 {%0,%1}, %2;" : "=f"(f.x), "=f"(f.y) : "l"(v));
    return f;
}

// ---- prep: repack weights so oc (or o) is contiguous per (c,kk) row ----
__global__ void prep_kernel(const float* __restrict__ weight,
                            const float* __restrict__ ow,
                            const float* __restrict__ mw) {
    int i = blockIdx.x * blockDim.x + threadIdx.x;
    if (i < 576 * COUT) {
        int ck = i >> 6;
        int oc = i & 63;
        g_wpack[i] = weight[oc * 576 + ck];
    }
    if (i < 576 * 28) {
        int ck = i / 28;
        int o = i - ck * 28;
        float v = 0.f;
        if (o < 18)      v = ow[o * 576 + ck];
        else if (o < 27) v = mw[(o - 18) * 576 + ck];
        g_opack[i] = v;
    }
}

// ---- kernel 1: fused offset+modulator 3x3 conv (27 outputs), tile 32x8 ----
__global__ __launch_bounds__(128) void conv_om_kernel(const float* __restrict__ x,
                                                      const float* __restrict__ ob,
                                                      const float* __restrict__ mb) {
    __shared__ float owS[144 * 28];   // 16 channels worth of packed weights (16128 B)
    __shared__ float sxt[4 * 340];    // 4-channel input tile, 10x34 each (5440 B)

    int tid = threadIdx.x;
    int tx = tid & 31;
    int tyq = tid >> 5;                 // 0..3; each thread handles rows tyq and tyq+4
    int tw0 = blockIdx.x * 32;
    int th0 = blockIdx.y * 8;
    int b = blockIdx.z;
    const float* xb = x + (size_t)b * CIN * HWSZ;

    unsigned long long acc0[14], acc1[14];
#pragma unroll
    for (int p = 0; p < 14; p++) { acc0[p] = 0ull; acc1[p] = 0ull; }

    for (int cc = 0; cc < 4; cc++) {
        __syncthreads();
        for (int i = tid; i < 144 * 28; i += 128)
            owS[i] = g_opack[cc * 144 * 28 + i];

        for (int cb = 0; cb < 4; cb++) {
            __syncthreads();
            int cbase = cc * 16 + cb * 4;
            for (int i = tid; i < 4 * 340; i += 128) {
                int c = cbase + i / 340;
                int rem = i % 340;
                int r = rem / 34;
                int cl2 = rem - r * 34;
                int gy = th0 - 1 + r;
                int gx = tw0 - 1 + cl2;
                float v = 0.f;
                if ((unsigned)gy < HH && (unsigned)gx < WW)
                    v = xb[c * HWSZ + gy * WW + gx];
                sxt[i] = v;
            }
            __syncthreads();
#pragma unroll 1
            for (int j = 0; j < 4; j++) {
                const float* s0 = &sxt[j * 340 + tyq * 34 + tx];
                int rowbase = ((cb * 4 + j) * 9) * 28;
#pragma unroll
                for (int kk = 0; kk < 9; kk++) {
                    const int ki = kk / 3, kj = kk % 3;
                    float xv0 = s0[ki * 34 + kj];
                    float xv1 = s0[(ki + 4) * 34 + kj];
                    const unsigned long long* wr =
                        (const unsigned long long*)&owS[rowbase + kk * 28];
                    unsigned long long v0 = pk2(xv0, xv0);
                    unsigned long long v1 = pk2(xv1, xv1);
#pragma unroll
                    for (int p = 0; p < 14; p++) {
                        unsigned long long w2 = wr[p];
                        fma2(acc0[p], v0, w2);
                        fma2(acc1[p], v1, w2);
                    }
                }
            }
        }
    }

    int y0 = th0 + tyq;
    int y1 = th0 + tyq + 4;
    int xo = tw0 + tx;
    float vals0[28], vals1[28];
#pragma unroll
    for (int p = 0; p < 14; p++) {
        float2 f0 = unpk2(acc0[p]), f1 = unpk2(acc1[p]);
        vals0[2 * p] = f0.x; vals0[2 * p + 1] = f0.y;
        vals1[2 * p] = f1.x; vals1[2 * p + 1] = f1.y;
    }
#pragma unroll
    for (int o = 0; o < 27; o++) {
        float v0 = vals0[o], v1 = vals1[o];
        if (o < 18) {
            float bb = ob[o];
            v0 += bb; v1 += bb;
        } else {
            float bb = mb[o - 18];
            v0 = 2.f / (1.f + __expf(-(v0 + bb)));
            v1 = 2.f / (1.f + __expf(-(v1 + bb)));
        }
        float* dst = &g_off[((size_t)b * 27 + o) * HWSZ];
        dst[y0 * WW + xo] = v0;
        dst[y1 * WW + xo] = v1;
    }
}

// ---- bilinear tap metadata ----
struct Tap { float a00, a01, a10, a11; int o00, o01, o10, o11; };

static __device__ __forceinline__ Tap mk_tap(const float* __restrict__ offb,
                                             int pos, int ho, int xi,
                                             int ki, int kj) {
    Tap t;
    float dy = offb[(2 * ki * 3 + 2 * kj) * HWSZ + pos];
    float dx = offb[(2 * ki * 3 + 2 * kj + 1) * HWSZ + pos];
    float m  = offb[(18 + ki * 3 + kj) * HWSZ + pos];
    float fy = (float)(ho - 1 + ki) + dy;
    float fx = (float)(xi - 1 + kj) + dx;
    float fy0 = floorf(fy), fx0 = floorf(fx);
    int iy0 = (int)fy0, ix0 = (int)fx0;
    float wy = fy - fy0, wx = fx - fx0;
    bool vy0 = (unsigned)iy0 < HH;
    bool vy1 = (unsigned)(iy0 + 1) < HH;
    bool vx0 = (unsigned)ix0 < WW;
    bool vx1 = (unsigned)(ix0 + 1) < WW;
    t.a00 = (1.f - wy) * (1.f - wx) * m * ((vy0 && vx0) ? 1.f : 0.f);
    t.a01 = (1.f - wy) * wx         * m * ((vy0 && vx1) ? 1.f : 0.f);
    t.a10 = wy * (1.f - wx)         * m * ((vy1 && vx0) ? 1.f : 0.f);
    t.a11 = wy * wx                 * m * ((vy1 && vx1) ? 1.f : 0.f);
    int cy0 = min(max(iy0, 0), HH - 1);
    int cy1 = min(max(iy0 + 1, 0), HH - 1);
    int cx0 = min(max(ix0, 0), WW - 1);
    int cx1 = min(max(ix0 + 1, 0), WW - 1);
    t.o00 = cy0 * WW + cx0; t.o01 = cy0 * WW + cx1;
    t.o10 = cy1 * WW + cx0; t.o11 = cy1 * WW + cx1;
    return t;
}

// ---- kernel 2 v3: software-pipelined gather->smem + register-tiled GEMM ----
// Block = 256 threads = one row (128 pos) x 64 oc.
// Stage role: thread = (pos sp, channel-half cl0): gathers 8 channels for 1 pos.
// GEMM role:  thread = 4 pos x 8 oc (16 u64 accumulators).
// Double-buffered vS; LDGs for iter k+1 issued before GEMM of iter k.
__global__ __launch_bounds__(256, 2) void deform_kernel(const float* __restrict__ x,
                                                        float* __restrict__ out) {
    __shared__ float wS[16 * 9 * 64];       // 36864 B
    __shared__ float vS[2][16][128];        // 16384 B

    int t = threadIdx.x;
    int ho = blockIdx.x;
    int b = blockIdx.y;
    const float* xb = x + (size_t)b * CIN * HWSZ;
    const float* offb = g_off + (size_t)b * 27 * HWSZ;

    // staging role
    int sp = t & 127;               // position in row
    int cl0 = (t >> 7) * 8;         // first of 8 channels within 16-chunk
    int spos = ho * WW + sp;

    // gemm role
    int og = t & 7;                 // oc0a = og*4, oc0b = og*4+32
    int pg = t >> 3;                // pos0 = pg*4
    int pos0 = pg * 4;

    unsigned long long acc[4][4];   // [pos j][oc quad q]: q0,q1 -> og*4+{0,2}; q2,q3 -> og*4+32+{0,2}
#pragma unroll
    for (int j = 0; j < 4; j++)
#pragma unroll
        for (int q = 0; q < 4; q++) acc[j][q] = 0ull;

    float raw[32];
    Tap tp;

    // prologue: prefetch iteration 0 (cc=0, kk=0)
    {
        tp = mk_tap(offb, spos, ho, sp, 0, 0);
        const float* xc = xb + cl0 * HWSZ;
#pragma unroll
        for (int i = 0; i < 8; i++) {
            const float* p = xc + i * HWSZ;
            raw[4 * i]     = __ldg(p + tp.o00);
            raw[4 * i + 1] = __ldg(p + tp.o01);
            raw[4 * i + 2] = __ldg(p + tp.o10);
            raw[4 * i + 3] = __ldg(p + tp.o11);
        }
    }

    Tap ctap = tp;  // tap for current (combine) iteration

#pragma unroll 1
    for (int it = 0; it < 36; it++) {
        int cc = it / 9;
        int kk = it - cc * 9;

        if (kk == 0) {
            __syncthreads();   // all GEMM reads of old wS done
            const float4* src = (const float4*)(g_wpack + cc * 9216);
            float4* dst = (float4*)wS;
#pragma unroll
            for (int i = 0; i < 9; i++)
                dst[t + i * 256] = src[t + i * 256];
        }

        // combine raw -> v, store to vS[it&1]
        int buf = it & 1;
#pragma unroll
        for (int i = 0; i < 8; i++) {
            float v = ctap.a00 * raw[4 * i]     + ctap.a01 * raw[4 * i + 1]
                    + ctap.a10 * raw[4 * i + 2] + ctap.a11 * raw[4 * i + 3];
            vS[buf][cl0 + i][sp] = v;
        }
        __syncthreads();       // vS (and wS at kk==0) visible

        // prefetch next iteration's gathers (fly during GEMM below)
        if (it + 1 < 36) {
            int itn = it + 1;
            int ccn = itn / 9;
            int kkn = itn - ccn * 9;
            int kin = kkn / 3, kjn = kkn - kin * 3;
            tp = mk_tap(offb, spos, ho, sp, kin, kjn);
            const float* xc = xb + (ccn * 16 + cl0) * HWSZ;
#pragma unroll
            for (int i = 0; i < 8; i++) {
                const float* p = xc + i * HWSZ;
                raw[4 * i]     = __ldg(p + tp.o00);
                raw[4 * i + 1] = __ldg(p + tp.o01);
                raw[4 * i + 2] = __ldg(p + tp.o10);
                raw[4 * i + 3] = __ldg(p + tp.o11);
            }
        }

        // GEMM: 16 channels, 4 pos x 8 oc per thread
#pragma unroll
        for (int cl = 0; cl < 16; cl++) {
            float4 v4 = *(const float4*)&vS[buf][cl][pos0];
            const float* wrow = &wS[(cl * 9 + kk) * 64];
            ulonglong2 wA = *(const ulonglong2*)&wrow[og * 4];        // oc og*4..+3
            ulonglong2 wB = *(const ulonglong2*)&wrow[og * 4 + 32];   // oc og*4+32..+35
            unsigned long long vv;
            vv = pk2(v4.x, v4.x);
            fma2(acc[0][0], vv, wA.x); fma2(acc[0][1], vv, wA.y);
            fma2(acc[0][2], vv, wB.x); fma2(acc[0][3], vv, wB.y);
            vv = pk2(v4.y, v4.y);
            fma2(acc[1][0], vv, wA.x); fma2(acc[1][1], vv, wA.y);
            fma2(acc[1][2], vv, wB.x); fma2(acc[1][3], vv, wB.y);
            vv = pk2(v4.z, v4.z);
            fma2(acc[2][0], vv, wA.x); fma2(acc[2][1], vv, wA.y);
            fma2(acc[2][2], vv, wB.x); fma2(acc[2][3], vv, wB.y);
            vv = pk2(v4.w, v4.w);
            fma2(acc[3][0], vv, wA.x); fma2(acc[3][1], vv, wA.y);
            fma2(acc[3][2], vv, wB.x); fma2(acc[3][3], vv, wB.y);
        }
        ctap = tp;
    }

    // epilogue: write 4 pos x 8 oc
    float* ob = out + (size_t)b * COUT * HWSZ + ho * WW;
#pragma unroll
    for (int j = 0; j < 4; j++) {
#pragma unroll
        for (int q = 0; q < 4; q++) {
            int oc = (q < 2) ? (og * 4 + 2 * q) : (og * 4 + 32 + 2 * (q - 2));
            float2 f = unpk2(acc[j][q]);
            ob[(size_t)oc * HWSZ + pos0 + j] = f.x;
            ob[(size_t)(oc + 1) * HWSZ + pos0 + j] = f.y;
        }
    }
}

extern "C" void kernel_launch(void* const* d_in, const int* in_sizes, int n_in,
                              void* d_out, int out_size) {
    const float* x  = (const float*)d_in[0];  // [8,64,128,128]
    const float* ow = (const float*)d_in[1];  // [18,64,3,3]
    const float* ob = (const float*)d_in[2];  // [18]
    const float* mw = (const float*)d_in[3];  // [9,64,3,3]
    const float* mb = (const float*)d_in[4];  // [9]
    const float* wt = (const float*)d_in[5];  // [64,64,3,3]
    float* out = (float*)d_out;               // [8,64,128,128]

    prep_kernel<<<144, 256>>>(wt, ow, mw);

    dim3 g1(WW / 32, HH / 8, BATCH);
    conv_om_kernel<<<g1, 128>>>(x, ob, mb);

    dim3 g2(HH, BATCH);
    deform_kernel<<<g2, 256>>>(x, out);
}

// round 7
// speedup vs baseline: 1.6228x; 1.2231x over previous
#include <cuda_runtime.h>
#include <cuda_bf16.h>
#include <cstdint>

#define HH 128
#define WW 128
#define HWSZ (128*128)
#define CIN 64
#define COUT 64
#define BATCH 8

// scratch (__device__ globals: allocation-free)
__device__ float g_off[BATCH * 27 * HWSZ];   // [b][27][H][W]
__device__ float g_opack[576 * 28];          // offset/mod conv weights, o-contiguous
// B weight fragments for mma.sync m16n8k16: u32 index = ((s*8 + j)*32 + lane)*2 + b
// s = kk*4+cc (36 steps), j = n8 block (8), b = k-half (2). hi / lo bf16 split planes.
__device__ uint32_t g_wfh[36 * 8 * 32 * 2];
__device__ uint32_t g_wfl[36 * 8 * 32 * 2];

// ---- packed f32x2 helpers (conv_om kernel) ----
static __device__ __forceinline__ unsigned long long pk2(float lo, float hi) {
    unsigned long long r;
    asm("mov.b64 %0, {%1,%2};" : "=l"(r) : "f"(lo), "f"(hi));
    return r;
}
static __device__ __forceinline__ void fma2(unsigned long long& d,
                                            unsigned long long a,
                                            unsigned long long b) {
    asm("fma.rn.f32x2 %0, %1, %2, %0;" : "+l"(d) : "l"(a), "l"(b));
}
static __device__ __forceinline__ float2 unpk2(unsigned long long v) {
    float2 f;
    asm("mov.b64 {%0,%1}, %2;" : "=f"(f.x), "=f"(f.y) : "l"(v));
    return f;
}

static __device__ __forceinline__ uint32_t bf16pk(float a, float b) {
    __nv_bfloat16 ha = __float2bfloat16(a);
    __nv_bfloat16 hb = __float2bfloat16(b);
    return (uint32_t)__bfloat16_as_ushort(ha)
         | ((uint32_t)__bfloat16_as_ushort(hb) << 16);
}

// ---- prep: pack conv_om weights + main-weight HMMA fragments (hi/lo split) ----
__global__ void prep_kernel(const float* __restrict__ weight,
                            const float* __restrict__ ow,
                            const float* __restrict__ mw) {
    int i = blockIdx.x * blockDim.x + threadIdx.x;
    if (i < 576 * 28) {
        int ck = i / 28;
        int o = i - ck * 28;
        float v = 0.f;
        if (o < 18)      v = ow[o * 576 + ck];
        else if (o < 27) v = mw[(o - 18) * 576 + ck];
        g_opack[i] = v;
    }
    if (i < 36 * 8 * 32 * 2) {
        int bb = i & 1;
        int lane = (i >> 1) & 31;
        int j = (i >> 6) & 7;
        int s = i >> 9;                 // 0..35
        int kk = s >> 2;
        int cc = s & 3;
        int kr = 2 * (lane & 3) + 8 * bb;
        int oc = j * 8 + (lane >> 2);
        int c0 = cc * 16 + kr;
        float w0 = weight[oc * 576 + c0 * 9 + kk];
        float w1 = weight[oc * 576 + (c0 + 1) * 9 + kk];
        __nv_bfloat16 h0 = __float2bfloat16(w0);
        __nv_bfloat16 h1 = __float2bfloat16(w1);
        float l0 = w0 - __bfloat162float(h0);
        float l1 = w1 - __bfloat162float(h1);
        g_wfh[i] = (uint32_t)__bfloat16_as_ushort(h0)
                 | ((uint32_t)__bfloat16_as_ushort(h1) << 16);
        g_wfl[i] = bf16pk(l0, l1);
    }
}

// ---- kernel 1: fused offset+modulator 3x3 conv (27 outputs), tile 32x8 ----
__global__ __launch_bounds__(128) void conv_om_kernel(const float* __restrict__ x,
                                                      const float* __restrict__ ob,
                                                      const float* __restrict__ mb) {
    __shared__ float owS[144 * 28];
    __shared__ float sxt[4 * 340];

    int tid = threadIdx.x;
    int tx = tid & 31;
    int tyq = tid >> 5;
    int tw0 = blockIdx.x * 32;
    int th0 = blockIdx.y * 8;
    int b = blockIdx.z;
    const float* xb = x + (size_t)b * CIN * HWSZ;

    unsigned long long acc0[14], acc1[14];
#pragma unroll
    for (int p = 0; p < 14; p++) { acc0[p] = 0ull; acc1[p] = 0ull; }

    for (int cc = 0; cc < 4; cc++) {
        __syncthreads();
        for (int i = tid; i < 144 * 28; i += 128)
            owS[i] = g_opack[cc * 144 * 28 + i];

        for (int cb = 0; cb < 4; cb++) {
            __syncthreads();
            int cbase = cc * 16 + cb * 4;
            for (int i = tid; i < 4 * 340; i += 128) {
                int c = cbase + i / 340;
                int rem = i % 340;
                int r = rem / 34;
                int cl2 = rem - r * 34;
                int gy = th0 - 1 + r;
                int gx = tw0 - 1 + cl2;
                float v = 0.f;
                if ((unsigned)gy < HH && (unsigned)gx < WW)
                    v = xb[c * HWSZ + gy * WW + gx];
                sxt[i] = v;
            }
            __syncthreads();
#pragma unroll 1
            for (int j = 0; j < 4; j++) {
                const float* s0 = &sxt[j * 340 + tyq * 34 + tx];
                int rowbase = ((cb * 4 + j) * 9) * 28;
#pragma unroll
                for (int kk = 0; kk < 9; kk++) {
                    const int ki = kk / 3, kj = kk % 3;
                    float xv0 = s0[ki * 34 + kj];
                    float xv1 = s0[(ki + 4) * 34 + kj];
                    const unsigned long long* wr =
                        (const unsigned long long*)&owS[rowbase + kk * 28];
                    unsigned long long v0 = pk2(xv0, xv0);
                    unsigned long long v1 = pk2(xv1, xv1);
#pragma unroll
                    for (int p = 0; p < 14; p++) {
                        unsigned long long w2 = wr[p];
                        fma2(acc0[p], v0, w2);
                        fma2(acc1[p], v1, w2);
                    }
                }
            }
        }
    }

    int y0 = th0 + tyq;
    int y1 = th0 + tyq + 4;
    int xo = tw0 + tx;
    float vals0[28], vals1[28];
#pragma unroll
    for (int p = 0; p < 14; p++) {
        float2 f0 = unpk2(acc0[p]), f1 = unpk2(acc1[p]);
        vals0[2 * p] = f0.x; vals0[2 * p + 1] = f0.y;
        vals1[2 * p] = f1.x; vals1[2 * p + 1] = f1.y;
    }
#pragma unroll
    for (int o = 0; o < 27; o++) {
        float v0 = vals0[o], v1 = vals1[o];
        if (o < 18) {
            float bb = ob[o];
            v0 += bb; v1 += bb;
        } else {
            float bb = mb[o - 18];
            v0 = 2.f / (1.f + __expf(-(v0 + bb)));
            v1 = 2.f / (1.f + __expf(-(v1 + bb)));
        }
        float* dst = &g_off[((size_t)b * 27 + o) * HWSZ];
        dst[y0 * WW + xo] = v0;
        dst[y1 * WW + xo] = v1;
    }
}

// ---- bilinear tap metadata ----
struct Tap { float a00, a01, a10, a11; int o00, o01, o10, o11; };

static __device__ __forceinline__ Tap mk_tap(const float* __restrict__ offb,
                                             int pos, int ho, int xi,
                                             int ki, int kj) {
    Tap t;
    float dy = offb[(2 * ki * 3 + 2 * kj) * HWSZ + pos];
    float dx = offb[(2 * ki * 3 + 2 * kj + 1) * HWSZ + pos];
    float m  = offb[(18 + ki * 3 + kj) * HWSZ + pos];
    float fy = (float)(ho - 1 + ki) + dy;
    float fx = (float)(xi - 1 + kj) + dx;
    float fy0 = floorf(fy), fx0 = floorf(fx);
    int iy0 = (int)fy0, ix0 = (int)fx0;
    float wy = fy - fy0, wx = fx - fx0;
    bool vy0 = (unsigned)iy0 < HH;
    bool vy1 = (unsigned)(iy0 + 1) < HH;
    bool vx0 = (unsigned)ix0 < WW;
    bool vx1 = (unsigned)(ix0 + 1) < WW;
    t.a00 = (1.f - wy) * (1.f - wx) * m * ((vy0 && vx0) ? 1.f : 0.f);
    t.a01 = (1.f - wy) * wx         * m * ((vy0 && vx1) ? 1.f : 0.f);
    t.a10 = wy * (1.f - wx)         * m * ((vy1 && vx0) ? 1.f : 0.f);
    t.a11 = wy * wx                 * m * ((vy1 && vx1) ? 1.f : 0.f);
    int cy0 = min(max(iy0, 0), HH - 1);
    int cy1 = min(max(iy0 + 1, 0), HH - 1);
    int cx0 = min(max(ix0, 0), WW - 1);
    int cx1 = min(max(ix0 + 1, 0), WW - 1);
    t.o00 = cy0 * WW + cx0; t.o01 = cy0 * WW + cx1;
    t.o10 = cy1 * WW + cx0; t.o11 = cy1 * WW + cx1;
    return t;
}

static __device__ __forceinline__ void mma_bf16(float* d, uint32_t a0, uint32_t a1,
                                                uint32_t a2, uint32_t a3,
                                                uint32_t b0, uint32_t b1) {
    asm volatile(
        "mma.sync.aligned.m16n8k16.row.col.f32.bf16.bf16.f32 "
        "{%0,%1,%2,%3}, {%4,%5,%6,%7}, {%8,%9}, {%0,%1,%2,%3};"
        : "+f"(d[0]), "+f"(d[1]), "+f"(d[2]), "+f"(d[3])
        : "r"(a0), "r"(a1), "r"(a2), "r"(a3), "r"(b0), "r"(b1));
}

// ---- kernel 2 v5: pipelined gather -> bf16-split smem -> HMMA (mma.sync) ----
// Block = 256 threads = one row (128 pos) x 64 oc, K=576 as 36 steps of 16.
// Step s = kk*4+cc (kk outer: tap computed once per kk).
// Warp w computes pos tile [16w,16w+16) x all 64 oc (8 n8 frags).
__global__ __launch_bounds__(256, 2) void deform_kernel(const float* __restrict__ x,
                                                        float* __restrict__ out) {
    __shared__ uint32_t wBh[4 * 8 * 32 * 2];                       // 8 KB
    __shared__ uint32_t wBl[4 * 8 * 32 * 2];                       // 8 KB
    __shared__ __align__(16) unsigned short vSh[2][128][16];       // 8 KB
    __shared__ __align__(16) unsigned short vSl[2][128][16];       // 8 KB

    int t = threadIdx.x;
    int wid = t >> 5;
    int lid = t & 31;
    int ho = blockIdx.x;
    int b = blockIdx.y;
    const float* xb = x + (size_t)b * CIN * HWSZ;
    const float* offb = g_off + (size_t)b * 27 * HWSZ;

    // staging role
    int sp = t & 127;
    int cl0 = (t >> 7) * 8;
    int spos = ho * WW + sp;

    // gemm role
    int pos0 = wid * 16;
    int r4 = lid >> 2;
    int q4 = lid & 3;

    float acc[8][4];
#pragma unroll
    for (int j = 0; j < 8; j++)
#pragma unroll
        for (int q = 0; q < 4; q++) acc[j][q] = 0.f;

    Tap tp = mk_tap(offb, spos, ho, sp, 0, 0);

    // prologue: fill vS[0] for step 0 (kk=0, cc=0)
    {
        const float* xc = xb + cl0 * HWSZ;
        float v[8];
#pragma unroll
        for (int i = 0; i < 8; i++) {
            const float* p = xc + i * HWSZ;
            v[i] = tp.a00 * __ldg(p + tp.o00) + tp.a01 * __ldg(p + tp.o01)
                 + tp.a10 * __ldg(p + tp.o10) + tp.a11 * __ldg(p + tp.o11);
        }
        uint32_t ph[4], pl[4];
#pragma unroll
        for (int j = 0; j < 4; j++) {
            __nv_bfloat16 h0 = __float2bfloat16(v[2 * j]);
            __nv_bfloat16 h1 = __float2bfloat16(v[2 * j + 1]);
            ph[j] = (uint32_t)__bfloat16_as_ushort(h0)
                  | ((uint32_t)__bfloat16_as_ushort(h1) << 16);
            pl[j] = bf16pk(v[2 * j] - __bfloat162float(h0),
                           v[2 * j + 1] - __bfloat162float(h1));
        }
        *(uint4*)&vSh[0][sp][cl0] = make_uint4(ph[0], ph[1], ph[2], ph[3]);
        *(uint4*)&vSl[0][sp][cl0] = make_uint4(pl[0], pl[1], pl[2], pl[3]);
    }

#pragma unroll 1
    for (int it = 0; it < 36; it++) {
        int kk = it >> 2;
        int cc = it & 3;
        int buf = it & 1;

        __syncthreads();   // vS[buf] visible; previous GEMM done (safe wB reload)

        if (cc == 0) {
            const uint4* sh = (const uint4*)(g_wfh + kk * 2048);
            const uint4* sl = (const uint4*)(g_wfl + kk * 2048);
            ((uint4*)wBh)[t] = sh[t]; ((uint4*)wBh)[t + 256] = sh[t + 256];
            ((uint4*)wBl)[t] = sl[t]; ((uint4*)wBl)[t + 256] = sl[t + 256];
        }

        // prefetch next step into the other vS buffer
        if (it + 1 < 36) {
            int itn = it + 1;
            int kkn = itn >> 2;
            int ccn = itn & 3;
            if (ccn == 0) tp = mk_tap(offb, spos, ho, sp, kkn / 3, kkn % 3);
            const float* xc = xb + (ccn * 16 + cl0) * HWSZ;
            float v[8];
#pragma unroll
            for (int i = 0; i < 8; i++) {
                const float* p = xc + i * HWSZ;
                v[i] = tp.a00 * __ldg(p + tp.o00) + tp.a01 * __ldg(p + tp.o01)
                     + tp.a10 * __ldg(p + tp.o10) + tp.a11 * __ldg(p + tp.o11);
            }
            uint32_t ph[4], pl[4];
#pragma unroll
            for (int j = 0; j < 4; j++) {
                __nv_bfloat16 h0 = __float2bfloat16(v[2 * j]);
                __nv_bfloat16 h1 = __float2bfloat16(v[2 * j + 1]);
                ph[j] = (uint32_t)__bfloat16_as_ushort(h0)
                      | ((uint32_t)__bfloat16_as_ushort(h1) << 16);
                pl[j] = bf16pk(v[2 * j] - __bfloat162float(h0),
                               v[2 * j + 1] - __bfloat162float(h1));
            }
            int nb = itn & 1;
            *(uint4*)&vSh[nb][sp][cl0] = make_uint4(ph[0], ph[1], ph[2], ph[3]);
            *(uint4*)&vSl[nb][sp][cl0] = make_uint4(pl[0], pl[1], pl[2], pl[3]);
        }

        if (cc == 0) __syncthreads();   // wB visible

        // GEMM: one k16 step, 8 n8 fragments, hi/lo split (3 MMAs each)
        {
            const char* bhp = (const char*)&vSh[buf][0][0];
            const char* blp = (const char*)&vSl[buf][0][0];
            uint32_t aoff = (uint32_t)((pos0 + r4) * 32 + q4 * 4);
            uint32_t ah0 = *(const uint32_t*)(bhp + aoff);
            uint32_t ah1 = *(const uint32_t*)(bhp + aoff + 256);
            uint32_t ah2 = *(const uint32_t*)(bhp + aoff + 16);
            uint32_t ah3 = *(const uint32_t*)(bhp + aoff + 256 + 16);
            uint32_t al0 = *(const uint32_t*)(blp + aoff);
            uint32_t al1 = *(const uint32_t*)(blp + aoff + 256);
            uint32_t al2 = *(const uint32_t*)(blp + aoff + 16);
            uint32_t al3 = *(const uint32_t*)(blp + aoff + 256 + 16);
            const uint2* wbh = (const uint2*)&wBh[cc * 512];
            const uint2* wbl = (const uint2*)&wBl[cc * 512];
#pragma unroll
            for (int j = 0; j < 8; j++) {
                uint2 bh2 = wbh[j * 32 + lid];
                uint2 bl2 = wbl[j * 32 + lid];
                mma_bf16(acc[j], ah0, ah1, ah2, ah3, bh2.x, bh2.y);
                mma_bf16(acc[j], ah0, ah1, ah2, ah3, bl2.x, bl2.y);
                mma_bf16(acc[j], al0, al1, al2, al3, bh2.x, bh2.y);
            }
        }
    }

    // epilogue: warp w owns pos [16w,16w+16), all 64 oc
    float* ob = out + (size_t)b * COUT * HWSZ + ho * WW;
#pragma unroll
    for (int j = 0; j < 8; j++) {
        int oc = j * 8 + q4 * 2;
        int p = pos0 + r4;
        ob[(size_t)oc * HWSZ + p]           = acc[j][0];
        ob[(size_t)(oc + 1) * HWSZ + p]     = acc[j][1];
        ob[(size_t)oc * HWSZ + p + 8]       = acc[j][2];
        ob[(size_t)(oc + 1) * HWSZ + p + 8] = acc[j][3];
    }
}

extern "C" void kernel_launch(void* const* d_in, const int* in_sizes, int n_in,
                              void* d_out, int out_size) {
    const float* x  = (const float*)d_in[0];  // [8,64,128,128]
    const float* ow = (const float*)d_in[1];  // [18,64,3,3]
    const float* ob = (const float*)d_in[2];  // [18]
    const float* mw = (const float*)d_in[3];  // [9,64,3,3]
    const float* mb = (const float*)d_in[4];  // [9]
    const float* wt = (const float*)d_in[5];  // [64,64,3,3]
    float* out = (float*)d_out;               // [8,64,128,128]

    prep_kernel<<<72, 256>>>(wt, ow, mw);

    dim3 g1(WW / 32, HH / 8, BATCH);
    conv_om_kernel<<<g1, 128>>>(x, ob, mb);

    dim3 g2(HH, BATCH);
    deform_kernel<<<g2, 256>>>(x, out);
}

// round 8
// speedup vs baseline: 1.7720x; 1.0920x over previous
#include <cuda_runtime.h>
#include <cuda_bf16.h>
#include <cstdint>

#define HH 128
#define WW 128
#define HWSZ (128*128)
#define CIN 64
#define COUT 64
#define BATCH 8

// scratch (__device__ globals: allocation-free)
__device__ float g_off[BATCH * 27 * HWSZ];   // [b][27][H][W]
// B weight fragments for mma.sync m16n8k16, main weights:
// u32 index = ((s*8 + j)*32 + lane)*2 + b ; s = kk*4+cc, j = n8 block(8), b = k-half
__device__ uint32_t g_wfh[36 * 8 * 32 * 2];
__device__ uint32_t g_wfl[36 * 8 * 32 * 2];
// conv_om weight fragments (N=32: 27 outputs zero-padded), 4 n8 blocks
__device__ uint32_t g_cfh[36 * 4 * 32 * 2];
__device__ uint32_t g_cfl[36 * 4 * 32 * 2];

static __device__ __forceinline__ uint32_t bf16pk(float a, float b) {
    __nv_bfloat16 ha = __float2bfloat16(a);
    __nv_bfloat16 hb = __float2bfloat16(b);
    return (uint32_t)__bfloat16_as_ushort(ha)
         | ((uint32_t)__bfloat16_as_ushort(hb) << 16);
}

// ---- prep: pack both weight sets into HMMA fragments (bf16 hi/lo split) ----
__global__ void prep_kernel(const float* __restrict__ weight,
                            const float* __restrict__ ow,
                            const float* __restrict__ mw) {
    int i = blockIdx.x * blockDim.x + threadIdx.x;
    if (i < 36 * 8 * 32 * 2) {
        int bb = i & 1;
        int lane = (i >> 1) & 31;
        int j = (i >> 6) & 7;
        int s = i >> 9;                 // 0..35
        int kk = s >> 2;
        int cc = s & 3;
        int kr = 2 * (lane & 3) + 8 * bb;
        int oc = j * 8 + (lane >> 2);
        int c0 = cc * 16 + kr;
        float w0 = weight[oc * 576 + c0 * 9 + kk];
        float w1 = weight[oc * 576 + (c0 + 1) * 9 + kk];
        __nv_bfloat16 h0 = __float2bfloat16(w0);
        __nv_bfloat16 h1 = __float2bfloat16(w1);
        g_wfh[i] = (uint32_t)__bfloat16_as_ushort(h0)
                 | ((uint32_t)__bfloat16_as_ushort(h1) << 16);
        g_wfl[i] = bf16pk(w0 - __bfloat162float(h0), w1 - __bfloat162float(h1));
    }
    if (i < 36 * 4 * 32 * 2) {
        int bb = i & 1;
        int lane = (i >> 1) & 31;
        int j = (i >> 6) & 3;
        int s = i >> 8;                 // 0..35
        int kk = s >> 2;
        int cc = s & 3;
        int kr = 2 * (lane & 3) + 8 * bb;
        int o = j * 8 + (lane >> 2);
        int c0 = cc * 16 + kr;
        float w0 = 0.f, w1 = 0.f;
        if (o < 18) {
            w0 = ow[o * 576 + c0 * 9 + kk];
            w1 = ow[o * 576 + (c0 + 1) * 9 + kk];
        } else if (o < 27) {
            w0 = mw[(o - 18) * 576 + c0 * 9 + kk];
            w1 = mw[(o - 18) * 576 + (c0 + 1) * 9 + kk];
        }
        __nv_bfloat16 h0 = __float2bfloat16(w0);
        __nv_bfloat16 h1 = __float2bfloat16(w1);
        g_cfh[i] = (uint32_t)__bfloat16_as_ushort(h0)
                 | ((uint32_t)__bfloat16_as_ushort(h1) << 16);
        g_cfl[i] = bf16pk(w0 - __bfloat162float(h0), w1 - __bfloat162float(h1));
    }
}

static __device__ __forceinline__ void mma_bf16(float* d, uint32_t a0, uint32_t a1,
                                                uint32_t a2, uint32_t a3,
                                                uint32_t b0, uint32_t b1) {
    asm volatile(
        "mma.sync.aligned.m16n8k16.row.col.f32.bf16.bf16.f32 "
        "{%0,%1,%2,%3}, {%4,%5,%6,%7}, {%8,%9}, {%0,%1,%2,%3};"
        : "+f"(d[0]), "+f"(d[1]), "+f"(d[2]), "+f"(d[3])
        : "r"(a0), "r"(a1), "r"(a2), "r"(a3), "r"(b0), "r"(b1));
}

// ---- kernel 1 v2: offset+modulator conv as pipelined HMMA GEMM ----
// Block = one row (128 pos), N=32 (27 real outputs), K=576 as 36 k16 steps.
__global__ __launch_bounds__(256, 2) void conv_om_kernel(const float* __restrict__ x,
                                                         const float* __restrict__ ob,
                                                         const float* __restrict__ mb) {
    __shared__ uint32_t wBh[4 * 4 * 32 * 2];                  // 4 KB
    __shared__ uint32_t wBl[4 * 4 * 32 * 2];                  // 4 KB
    __shared__ __align__(16) unsigned short vSh[2][128][16];  // 8 KB
    __shared__ __align__(16) unsigned short vSl[2][128][16];  // 8 KB

    int t = threadIdx.x;
    int wid = t >> 5;
    int lid = t & 31;
    int ho = blockIdx.x;
    int b = blockIdx.y;
    const float* xb = x + (size_t)b * CIN * HWSZ;

    int sp = t & 127;
    int cl0 = (t >> 7) * 8;

    int pos0 = wid * 16;
    int r4 = lid >> 2;
    int q4 = lid & 3;

    float acc[4][4];
#pragma unroll
    for (int j = 0; j < 4; j++)
#pragma unroll
        for (int q = 0; q < 4; q++) acc[j][q] = 0.f;

    // staging: step it -> vS[buf]
    auto stage = [&](int it, int buf) {
        int kk = it >> 2;
        int cc = it & 3;
        int ki = kk / 3, kj = kk - ki * 3;
        int yo = ho - 1 + ki;
        int xo = sp - 1 + kj;
        bool valid = ((unsigned)yo < HH) && ((unsigned)xo < WW);
        const float* xc = xb + (size_t)(cc * 16 + cl0) * HWSZ + yo * WW + xo;
        float v[8];
#pragma unroll
        for (int i = 0; i < 8; i++)
            v[i] = valid ? __ldg(xc + i * HWSZ) : 0.f;
        uint32_t ph[4], pl[4];
#pragma unroll
        for (int j = 0; j < 4; j++) {
            __nv_bfloat16 h0 = __float2bfloat16(v[2 * j]);
            __nv_bfloat16 h1 = __float2bfloat16(v[2 * j + 1]);
            ph[j] = (uint32_t)__bfloat16_as_ushort(h0)
                  | ((uint32_t)__bfloat16_as_ushort(h1) << 16);
            pl[j] = bf16pk(v[2 * j] - __bfloat162float(h0),
                           v[2 * j + 1] - __bfloat162float(h1));
        }
        *(uint4*)&vSh[buf][sp][cl0] = make_uint4(ph[0], ph[1], ph[2], ph[3]);
        *(uint4*)&vSl[buf][sp][cl0] = make_uint4(pl[0], pl[1], pl[2], pl[3]);
    };

    stage(0, 0);

#pragma unroll 1
    for (int it = 0; it < 36; it++) {
        int kk = it >> 2;
        int cc = it & 3;
        int buf = it & 1;

        __syncthreads();

        if (cc == 0) {
            ((uint4*)wBh)[t] = ((const uint4*)(g_cfh + kk * 1024))[t];
            ((uint4*)wBl)[t] = ((const uint4*)(g_cfl + kk * 1024))[t];
        }

        if (it + 1 < 36) stage(it + 1, buf ^ 1);

        if (cc == 0) __syncthreads();

        {
            const char* bhp = (const char*)&vSh[buf][0][0];
            const char* blp = (const char*)&vSl[buf][0][0];
            uint32_t aoff = (uint32_t)((pos0 + r4) * 32 + q4 * 4);
            uint32_t ah0 = *(const uint32_t*)(bhp + aoff);
            uint32_t ah1 = *(const uint32_t*)(bhp + aoff + 256);
            uint32_t ah2 = *(const uint32_t*)(bhp + aoff + 16);
            uint32_t ah3 = *(const uint32_t*)(bhp + aoff + 256 + 16);
            uint32_t al0 = *(const uint32_t*)(blp + aoff);
            uint32_t al1 = *(const uint32_t*)(blp + aoff + 256);
            uint32_t al2 = *(const uint32_t*)(blp + aoff + 16);
            uint32_t al3 = *(const uint32_t*)(blp + aoff + 256 + 16);
            const uint2* wbh = (const uint2*)&wBh[cc * 256];
            const uint2* wbl = (const uint2*)&wBl[cc * 256];
#pragma unroll
            for (int j = 0; j < 4; j++) {
                uint2 bh2 = wbh[j * 32 + lid];
                uint2 bl2 = wbl[j * 32 + lid];
                mma_bf16(acc[j], ah0, ah1, ah2, ah3, bh2.x, bh2.y);
                mma_bf16(acc[j], ah0, ah1, ah2, ah3, bl2.x, bl2.y);
                mma_bf16(acc[j], al0, al1, al2, al3, bh2.x, bh2.y);
            }
        }
    }

    // epilogue: bias / 2*sigmoid, write g_off planes (oc<27 guard)
    float* base = g_off + (size_t)b * 27 * HWSZ + ho * WW;
#pragma unroll
    for (int j = 0; j < 4; j++) {
        int oc0 = j * 8 + 2 * q4;
#pragma unroll
        for (int h = 0; h < 2; h++) {
            int o = oc0 + h;
            if (o < 27) {
                float v0 = acc[j][h];
                float v1 = acc[j][h + 2];
                if (o < 18) {
                    float bb = __ldg(ob + o);
                    v0 += bb; v1 += bb;
                } else {
                    float bb = __ldg(mb + o - 18);
                    v0 = 2.f / (1.f + __expf(-(v0 + bb)));
                    v1 = 2.f / (1.f + __expf(-(v1 + bb)));
                }
                base[(size_t)o * HWSZ + pos0 + r4] = v0;
                base[(size_t)o * HWSZ + pos0 + r4 + 8] = v1;
            }
        }
    }
}

// ---- bilinear tap metadata ----
struct Tap { float a00, a01, a10, a11; int o00, o01, o10, o11; };

static __device__ __forceinline__ Tap mk_tap(const float* __restrict__ offb,
                                             int pos, int ho, int xi,
                                             int ki, int kj) {
    Tap t;
    float dy = offb[(2 * ki * 3 + 2 * kj) * HWSZ + pos];
    float dx = offb[(2 * ki * 3 + 2 * kj + 1) * HWSZ + pos];
    float m  = offb[(18 + ki * 3 + kj) * HWSZ + pos];
    float fy = (float)(ho - 1 + ki) + dy;
    float fx = (float)(xi - 1 + kj) + dx;
    float fy0 = floorf(fy), fx0 = floorf(fx);
    int iy0 = (int)fy0, ix0 = (int)fx0;
    float wy = fy - fy0, wx = fx - fx0;
    bool vy0 = (unsigned)iy0 < HH;
    bool vy1 = (unsigned)(iy0 + 1) < HH;
    bool vx0 = (unsigned)ix0 < WW;
    bool vx1 = (unsigned)(ix0 + 1) < WW;
    t.a00 = (1.f - wy) * (1.f - wx) * m * ((vy0 && vx0) ? 1.f : 0.f);
    t.a01 = (1.f - wy) * wx         * m * ((vy0 && vx1) ? 1.f : 0.f);
    t.a10 = wy * (1.f - wx)         * m * ((vy1 && vx0) ? 1.f : 0.f);
    t.a11 = wy * wx                 * m * ((vy1 && vx1) ? 1.f : 0.f);
    int cy0 = min(max(iy0, 0), HH - 1);
    int cy1 = min(max(iy0 + 1, 0), HH - 1);
    int cx0 = min(max(ix0, 0), WW - 1);
    int cx1 = min(max(ix0 + 1, 0), WW - 1);
    t.o00 = cy0 * WW + cx0; t.o01 = cy0 * WW + cx1;
    t.o10 = cy1 * WW + cx0; t.o11 = cy1 * WW + cx1;
    return t;
}

// ---- kernel 2 v5: pipelined gather -> bf16-split smem -> HMMA (mma.sync) ----
__global__ __launch_bounds__(256, 2) void deform_kernel(const float* __restrict__ x,
                                                        float* __restrict__ out) {
    __shared__ uint32_t wBh[4 * 8 * 32 * 2];                       // 8 KB
    __shared__ uint32_t wBl[4 * 8 * 32 * 2];                       // 8 KB
    __shared__ __align__(16) unsigned short vSh[2][128][16];       // 8 KB
    __shared__ __align__(16) unsigned short vSl[2][128][16];       // 8 KB

    int t = threadIdx.x;
    int wid = t >> 5;
    int lid = t & 31;
    int ho = blockIdx.x;
    int b = blockIdx.y;
    const float* xb = x + (size_t)b * CIN * HWSZ;
    const float* offb = g_off + (size_t)b * 27 * HWSZ;

    int sp = t & 127;
    int cl0 = (t >> 7) * 8;
    int spos = ho * WW + sp;

    int pos0 = wid * 16;
    int r4 = lid >> 2;
    int q4 = lid & 3;

    float acc[8][4];
#pragma unroll
    for (int j = 0; j < 8; j++)
#pragma unroll
        for (int q = 0; q < 4; q++) acc[j][q] = 0.f;

    Tap tp = mk_tap(offb, spos, ho, sp, 0, 0);

    // prologue: fill vS[0] for step 0
    {
        const float* xc = xb + cl0 * HWSZ;
        float v[8];
#pragma unroll
        for (int i = 0; i < 8; i++) {
            const float* p = xc + i * HWSZ;
            v[i] = tp.a00 * __ldg(p + tp.o00) + tp.a01 * __ldg(p + tp.o01)
                 + tp.a10 * __ldg(p + tp.o10) + tp.a11 * __ldg(p + tp.o11);
        }
        uint32_t ph[4], pl[4];
#pragma unroll
        for (int j = 0; j < 4; j++) {
            __nv_bfloat16 h0 = __float2bfloat16(v[2 * j]);
            __nv_bfloat16 h1 = __float2bfloat16(v[2 * j + 1]);
            ph[j] = (uint32_t)__bfloat16_as_ushort(h0)
                  | ((uint32_t)__bfloat16_as_ushort(h1) << 16);
            pl[j] = bf16pk(v[2 * j] - __bfloat162float(h0),
                           v[2 * j + 1] - __bfloat162float(h1));
        }
        *(uint4*)&vSh[0][sp][cl0] = make_uint4(ph[0], ph[1], ph[2], ph[3]);
        *(uint4*)&vSl[0][sp][cl0] = make_uint4(pl[0], pl[1], pl[2], pl[3]);
    }

#pragma unroll 1
    for (int it = 0; it < 36; it++) {
        int kk = it >> 2;
        int cc = it & 3;
        int buf = it & 1;

        __syncthreads();

        if (cc == 0) {
            const uint4* sh = (const uint4*)(g_wfh + kk * 2048);
            const uint4* sl = (const uint4*)(g_wfl + kk * 2048);
            ((uint4*)wBh)[t] = sh[t]; ((uint4*)wBh)[t + 256] = sh[t + 256];
            ((uint4*)wBl)[t] = sl[t]; ((uint4*)wBl)[t + 256] = sl[t + 256];
        }

        if (it + 1 < 36) {
            int itn = it + 1;
            int kkn = itn >> 2;
            int ccn = itn & 3;
            if (ccn == 0) tp = mk_tap(offb, spos, ho, sp, kkn / 3, kkn % 3);
            const float* xc = xb + (ccn * 16 + cl0) * HWSZ;
            float v[8];
#pragma unroll
            for (int i = 0; i < 8; i++) {
                const float* p = xc + i * HWSZ;
                v[i] = tp.a00 * __ldg(p + tp.o00) + tp.a01 * __ldg(p + tp.o01)
                     + tp.a10 * __ldg(p + tp.o10) + tp.a11 * __ldg(p + tp.o11);
            }
            uint32_t ph[4], pl[4];
#pragma unroll
            for (int j = 0; j < 4; j++) {
                __nv_bfloat16 h0 = __float2bfloat16(v[2 * j]);
                __nv_bfloat16 h1 = __float2bfloat16(v[2 * j + 1]);
                ph[j] = (uint32_t)__bfloat16_as_ushort(h0)
                      | ((uint32_t)__bfloat16_as_ushort(h1) << 16);
                pl[j] = bf16pk(v[2 * j] - __bfloat162float(h0),
                               v[2 * j + 1] - __bfloat162float(h1));
            }
            int nb = itn & 1;
            *(uint4*)&vSh[nb][sp][cl0] = make_uint4(ph[0], ph[1], ph[2], ph[3]);
            *(uint4*)&vSl[nb][sp][cl0] = make_uint4(pl[0], pl[1], pl[2], pl[3]);
        }

        if (cc == 0) __syncthreads();

        {
            const char* bhp = (const char*)&vSh[buf][0][0];
            const char* blp = (const char*)&vSl[buf][0][0];
            uint32_t aoff = (uint32_t)((pos0 + r4) * 32 + q4 * 4);
            uint32_t ah0 = *(const uint32_t*)(bhp + aoff);
            uint32_t ah1 = *(const uint32_t*)(bhp + aoff + 256);
            uint32_t ah2 = *(const uint32_t*)(bhp + aoff + 16);
            uint32_t ah3 = *(const uint32_t*)(bhp + aoff + 256 + 16);
            uint32_t al0 = *(const uint32_t*)(blp + aoff);
            uint32_t al1 = *(const uint32_t*)(blp + aoff + 256);
            uint32_t al2 = *(const uint32_t*)(blp + aoff + 16);
            uint32_t al3 = *(const uint32_t*)(blp + aoff + 256 + 16);
            const uint2* wbh = (const uint2*)&wBh[cc * 512];
            const uint2* wbl = (const uint2*)&wBl[cc * 512];
#pragma unroll
            for (int j = 0; j < 8; j++) {
                uint2 bh2 = wbh[j * 32 + lid];
                uint2 bl2 = wbl[j * 32 + lid];
                mma_bf16(acc[j], ah0, ah1, ah2, ah3, bh2.x, bh2.y);
                mma_bf16(acc[j], ah0, ah1, ah2, ah3, bl2.x, bl2.y);
                mma_bf16(acc[j], al0, al1, al2, al3, bh2.x, bh2.y);
            }
        }
    }

    float* ob = out + (size_t)b * COUT * HWSZ + ho * WW;
#pragma unroll
    for (int j = 0; j < 8; j++) {
        int oc = j * 8 + q4 * 2;
        int p = pos0 + r4;
        ob[(size_t)oc * HWSZ + p]           = acc[j][0];
        ob[(size_t)(oc + 1) * HWSZ + p]     = acc[j][1];
        ob[(size_t)oc * HWSZ + p + 8]       = acc[j][2];
        ob[(size_t)(oc + 1) * HWSZ + p + 8] = acc[j][3];
    }
}

extern "C" void kernel_launch(void* const* d_in, const int* in_sizes, int n_in,
                              void* d_out, int out_size) {
    const float* x  = (const float*)d_in[0];  // [8,64,128,128]
    const float* ow = (const float*)d_in[1];  // [18,64,3,3]
    const float* ob = (const float*)d_in[2];  // [18]
    const float* mw = (const float*)d_in[3];  // [9,64,3,3]
    const float* mb = (const float*)d_in[4];  // [9]
    const float* wt = (const float*)d_in[5];  // [64,64,3,3]
    float* out = (float*)d_out;               // [8,64,128,128]

    prep_kernel<<<72, 256>>>(wt, ow, mw);

    dim3 g1(HH, BATCH);
    conv_om_kernel<<<g1, 256>>>(x, ob, mb);

    dim3 g2(HH, BATCH);
    deform_kernel<<<g2, 256>>>(x, out);
}